// round 8
// baseline (speedup 1.0000x reference)
#include <cuda_runtime.h>
#include <cuda_bf16.h>
#include <cstdint>
#include <cstddef>

#define Nn 8
#define Bb 4
#define Tt 1024
#define Dd 512
#define Hh 4
#define HDc 128
#define Rr 64
#define BTc (Bb*Tt)
#define NROWS (Nn*BTc)
#define EPSV 1e-5f
#define INV_SQRT_HD 0.08838834764831845f
#define L2E 1.4426950408889634f
#define FSTR 136
#define NT (Tt/64)

// ---------------- device scratch ----------------
__device__ float g_mu[NROWS];
__device__ float g_rs[NROWS];
__device__ float g_maskf[Nn];
__device__ float g_invna;
__device__ __nv_bfloat16 g_xh[(size_t)NROWS*Dd];
__device__ __nv_bfloat16 g_xl[(size_t)NROWS*Dd];
__device__ __nv_bfloat16 g_Wqh[Nn*Dd*Dd];
__device__ __nv_bfloat16 g_Woh[Nn*Dd*Dd];
__device__ float g_Sq[Nn*Dd];
__device__ float g_Cq[Nn*Dd];
__device__ float g_M[Nn*128*Dd];
__device__ __nv_bfloat16 g_Mbh[Nn*128*Dd];
__device__ __nv_bfloat16 g_Mbl[Nn*128*Dd];
__device__ float g_SM[Nn*128];
__device__ float g_CM[Nn*128];
__device__ float g_kq[(size_t)NROWS*Rr];
__device__ float g_vq[(size_t)NROWS*Rr];
__device__ float g_kdecT[Rr*Dd];
__device__ float g_vdecT[Rr*Dd];
__device__ __nv_bfloat16 g_Kh[(size_t)Bb*Hh*Tt*HDc];
__device__ __nv_bfloat16 g_Vh[(size_t)Bb*Hh*Tt*HDc];
__device__ __nv_bfloat16 g_Qh[(size_t)NROWS*Dd];
__device__ __nv_bfloat16 g_AOh[(size_t)NROWS*Dd];

// ---------------- helpers ----------------
__device__ __forceinline__ uint32_t pk2(float x, float y)
{
    __nv_bfloat162 h = __float22bfloat162_rn(make_float2(x, y));
    return *reinterpret_cast<uint32_t*>(&h);
}

__device__ __forceinline__ void ldsm4(uint32_t* r, const __nv_bfloat16* p)
{
    uint32_t a = (uint32_t)__cvta_generic_to_shared((void*)p);
    asm volatile("ldmatrix.sync.aligned.m8n8.x4.shared.b16 {%0,%1,%2,%3}, [%4];\n"
                 : "=r"(r[0]), "=r"(r[1]), "=r"(r[2]), "=r"(r[3]) : "r"(a));
}

__device__ __forceinline__ void ldsm4t(uint32_t* r, const __nv_bfloat16* p)
{
    uint32_t a = (uint32_t)__cvta_generic_to_shared((void*)p);
    asm volatile("ldmatrix.sync.aligned.m8n8.x4.trans.shared.b16 {%0,%1,%2,%3}, [%4];\n"
                 : "=r"(r[0]), "=r"(r[1]), "=r"(r[2]), "=r"(r[3]) : "r"(a));
}

__device__ __forceinline__ void mmabf(float* d, const uint32_t* a, uint32_t b0, uint32_t b1)
{
    asm volatile("mma.sync.aligned.m16n8k16.row.col.f32.bf16.bf16.f32 "
                 "{%0,%1,%2,%3},{%4,%5,%6,%7},{%8,%9},{%0,%1,%2,%3};\n"
                 : "+f"(d[0]), "+f"(d[1]), "+f"(d[2]), "+f"(d[3])
                 : "r"(a[0]), "r"(a[1]), "r"(a[2]), "r"(a[3]), "r"(b0), "r"(b1));
}

__device__ __forceinline__ void cpa16(const __nv_bfloat16* smem_dst, const __nv_bfloat16* gsrc)
{
    uint32_t ds = (uint32_t)__cvta_generic_to_shared((void*)smem_dst);
    asm volatile("cp.async.cg.shared.global [%0], [%1], 16;\n" :: "r"(ds), "l"(gsrc));
}
#define CPCOMMIT() asm volatile("cp.async.commit_group;\n" ::: "memory")
#define CPWAIT0()  asm volatile("cp.async.wait_group 0;\n" ::: "memory")

// ---------------- mask decode ----------------
__global__ void k_mask(const unsigned char* __restrict__ p)
{
    if (threadIdx.x == 0) {
        bool isF = (p[0]==0 && p[1]==0 && p[2]==0x80 && p[3]==0x3f);
        bool isI = (!isF && p[1]==0 && p[2]==0 && p[3]==0 && (p[4]!=0 || p[5]==0));
        float na = 0.f;
        for (int n = 0; n < Nn; n++) {
            bool bit;
            if (isF)      bit = (((const float*)p)[n] != 0.f);
            else if (isI) bit = (((const int*)p)[n]   != 0);
            else          bit = (p[n] != 0);
            g_maskf[n] = bit ? 1.f : 0.f;
            na += bit ? 1.f : 0.f;
        }
        g_invna = 1.f / fmaxf(na, 1.f);
    }
}

// ---------------- LN row stats + bf16 hi/lo copy of x ----------------
__global__ __launch_bounds__(256) void k_lnstats(const float* __restrict__ x)
{
    int row  = blockIdx.x * 8 + (threadIdx.x >> 5);
    int lane = threadIdx.x & 31;
    const float4* xp = (const float4*)(x + (size_t)row * Dd);
    float s = 0.f, sq = 0.f;
    #pragma unroll
    for (int i = 0; i < 4; i++) {
        int j = lane + 32*i;
        float4 v = xp[j];
        s  += v.x + v.y + v.z + v.w;
        sq += v.x*v.x + v.y*v.y + v.z*v.z + v.w*v.w;
        __nv_bfloat16 bx = __float2bfloat16(v.x);
        __nv_bfloat16 by = __float2bfloat16(v.y);
        __nv_bfloat16 bz = __float2bfloat16(v.z);
        __nv_bfloat16 bw = __float2bfloat16(v.w);
        __nv_bfloat162 h01; h01.x = bx; h01.y = by;
        __nv_bfloat162 h23; h23.x = bz; h23.y = bw;
        uint2 uh = make_uint2(*(uint32_t*)&h01, *(uint32_t*)&h23);
        uint2 ul = make_uint2(pk2(v.x - __bfloat162float(bx), v.y - __bfloat162float(by)),
                              pk2(v.z - __bfloat162float(bz), v.w - __bfloat162float(bw)));
        *(uint2*)(g_xh + (size_t)row*Dd + 4*j) = uh;
        *(uint2*)(g_xl + (size_t)row*Dd + 4*j) = ul;
    }
    #pragma unroll
    for (int o = 16; o > 0; o >>= 1) {
        s  += __shfl_xor_sync(0xffffffffu, s,  o);
        sq += __shfl_xor_sync(0xffffffffu, sq, o);
    }
    if (lane == 0) {
        float mu  = s * (1.f / Dd);
        float var = sq * (1.f / Dd) - mu * mu;
        g_mu[row] = mu;
        g_rs[row] = rsqrtf(var + EPSV);
    }
}

// ---------------- w_o -> bf16 ----------------
__global__ __launch_bounds__(256) void k_convwo(const float* __restrict__ wo)
{
    int idx = blockIdx.x * 256 + threadIdx.x;
    float4 v = ((const float4*)wo)[idx];
    ((uint2*)g_Woh)[idx] = make_uint2(pk2(v.x, v.y), pk2(v.z, v.w));
}

// ---------------- M_raw[n] = comp @ w ----------------
__global__ __launch_bounds__(256) void k_compgemm(
    const float* __restrict__ kcomp, const float* __restrict__ vcomp,
    const float* __restrict__ wk,    const float* __restrict__ wv)
{
    __shared__ float As[32*68];
    __shared__ float Bs[32*68];
    const int n    = blockIdx.x;
    const int half = blockIdx.y;
    const int i0   = blockIdx.z * 64;
    const float* comp = (half == 0 ? kcomp : vcomp) + (size_t)n * Rr * Dd;
    const float* w    = (half == 0 ? wk    : wv   ) + (size_t)n * Dd * Dd;
    const int tid = threadIdx.x, ty = tid >> 4, tx = tid & 15;
    const int arA = tid & 63, acA = (tid >> 6) * 8;
    const int arB = tid & 31, acB = (tid >> 5) * 8;

    float acc[4][4] = {};
    for (int k0 = 0; k0 < Dd; k0 += 32) {
        float4 a0 = *(const float4*)(comp + (size_t)arA*Dd + k0 + acA);
        float4 a1 = *(const float4*)(comp + (size_t)arA*Dd + k0 + acA + 4);
        float4 b0 = *(const float4*)(w + (size_t)(k0+arB)*Dd + i0 + acB);
        float4 b1 = *(const float4*)(w + (size_t)(k0+arB)*Dd + i0 + acB + 4);
        __syncthreads();
        As[(acA+0)*68+arA]=a0.x; As[(acA+1)*68+arA]=a0.y; As[(acA+2)*68+arA]=a0.z; As[(acA+3)*68+arA]=a0.w;
        As[(acA+4)*68+arA]=a1.x; As[(acA+5)*68+arA]=a1.y; As[(acA+6)*68+arA]=a1.z; As[(acA+7)*68+arA]=a1.w;
        *(float4*)&Bs[arB*68 + acB]     = b0;
        *(float4*)&Bs[arB*68 + acB + 4] = b1;
        __syncthreads();
        #pragma unroll
        for (int kk = 0; kk < 32; kk++) {
            float4 a  = *(const float4*)&As[kk*68 + ty*4];
            float4 bb = *(const float4*)&Bs[kk*68 + tx*4];
            float av[4] = {a.x,a.y,a.z,a.w};
            float bv[4] = {bb.x,bb.y,bb.z,bb.w};
            #pragma unroll
            for (int i = 0; i < 4; i++)
                #pragma unroll
                for (int j = 0; j < 4; j++)
                    acc[i][j] = fmaf(av[i], bv[j], acc[i][j]);
        }
    }
    #pragma unroll
    for (int i = 0; i < 4; i++) {
        int row = n*128 + half*64 + ty*4 + i;
        float4 o = make_float4(acc[i][0], acc[i][1], acc[i][2], acc[i][3]);
        *(float4*)(g_M + (size_t)row*Dd + i0 + tx*4) = o;
    }
}

// ---------------- fold LN(kv) into M -> bf16 hi/lo; SM/CM ----------------
__global__ __launch_bounds__(256) void k_foldM(const float* __restrict__ lnw,
                                               const float* __restrict__ lnb)
{
    int row  = blockIdx.x * 8 + (threadIdx.x >> 5);
    int lane = threadIdx.x & 31;
    int n = row >> 7;
    const float* lw = lnw + n*Dd;
    const float* lb = lnb + n*Dd;
    const float* Mrow = g_M + (size_t)row * Dd;
    float sm = 0.f, cm = 0.f;
    for (int i = lane; i < Dd; i += 32) {
        float m = Mrow[i], w = lw[i], b = lb[i];
        float p = w * m;
        sm += p; cm += b * m;
        __nv_bfloat16 hb = __float2bfloat16(p);
        g_Mbh[(size_t)row*Dd + i] = hb;
        g_Mbl[(size_t)row*Dd + i] = __float2bfloat16(p - __bfloat162float(hb));
    }
    #pragma unroll
    for (int o = 16; o > 0; o >>= 1) {
        sm += __shfl_xor_sync(0xffffffffu, sm, o);
        cm += __shfl_xor_sync(0xffffffffu, cm, o);
    }
    if (lane == 0) { g_SM[row] = sm; g_CM[row] = cm; }
}

// ---------------- fold LN(q) into w_q -> bf16 ----------------
__global__ __launch_bounds__(256) void k_foldQ(const float* __restrict__ lnw,
                                               const float* __restrict__ lnb,
                                               const float* __restrict__ wq)
{
    int row  = blockIdx.x * 8 + (threadIdx.x >> 5);
    int lane = threadIdx.x & 31;
    int n = row >> 9;
    const float* lw = lnw + n*Dd;
    const float* lb = lnb + n*Dd;
    const float* wr = wq + (size_t)row * Dd;
    float sm = 0.f, cm = 0.f;
    for (int i = lane; i < Dd; i += 32) {
        float m = wr[i], w = lw[i], b = lb[i];
        float p = w * m;
        sm += p; cm += b * m;
        g_Wqh[(size_t)row*Dd + i] = __float2bfloat16(p);
    }
    #pragma unroll
    for (int o = 16; o > 0; o >>= 1) {
        sm += __shfl_xor_sync(0xffffffffu, sm, o);
        cm += __shfl_xor_sync(0xffffffffu, cm, o);
    }
    if (lane == 0) { g_Sq[row] = sm; g_Cq[row] = cm; }
}

// ------- bf16 GEMM 128x128xK512 with cp.async pipeline. MODE 0 = Q, 1 = O -------
template<int MODE>
__global__ __launch_bounds__(256, 2) void k_hgemm(const float* __restrict__ X,
                                                  float* __restrict__ Out,
                                                  int ybase)
{
    __shared__ __nv_bfloat16 As[2][128*40];
    __shared__ __nv_bfloat16 Bs[2][128*40];
    const int m0 = (blockIdx.y + ybase) * 128;
    const int o0 = blockIdx.x * 128;
    const int n  = m0 >> 12;
    const __nv_bfloat16* A = (MODE == 0) ? g_xh : g_AOh;
    const __nv_bfloat16* B = ((MODE == 0) ? g_Wqh : g_Woh) + (size_t)n * Dd * Dd;

    const int tid = threadIdx.x, lane = tid & 31, warp = tid >> 5;
    const int wm = warp & 3, wn = warp >> 2;

    auto copyAB = [&](int st, int k0) {
        #pragma unroll
        for (int i = 0; i < 2; i++) {
            int idx = tid + i*256;
            int r = idx >> 2, c = (idx & 3) * 8;
            cpa16(&As[st][r*40 + c], A + (size_t)(m0 + r)*Dd + k0 + c);
            cpa16(&Bs[st][r*40 + c], B + (size_t)(o0 + r)*Dd + k0 + c);
        }
    };

    copyAB(0, 0);
    CPCOMMIT();

    float acc[2][8][4];
    #pragma unroll
    for (int i = 0; i < 2; i++)
        #pragma unroll
        for (int j = 0; j < 8; j++)
            #pragma unroll
            for (int k = 0; k < 4; k++) acc[i][j][k] = 0.f;

    const int arow = wm*32 + (lane & 15);
    const int acol = ((lane >> 4) & 1) * 8;
    const int brow = wn*64 + (lane & 7) + ((lane >> 4) & 1) * 8;
    const int bcol = ((lane >> 3) & 1) * 8;

    for (int ks = 0; ks < 16; ks++) {
        int st = ks & 1;
        CPWAIT0();
        __syncthreads();
        if (ks < 15) { copyAB(st ^ 1, (ks+1)*32); CPCOMMIT(); }

        const __nv_bfloat16* Asb = As[st];
        const __nv_bfloat16* Bsb = Bs[st];

        uint32_t af[2][2][4];
        #pragma unroll
        for (int mf = 0; mf < 2; mf++)
            #pragma unroll
            for (int kf = 0; kf < 2; kf++)
                ldsm4(af[mf][kf], Asb + (arow + mf*16)*40 + kf*16 + acol);

        #pragma unroll
        for (int ng = 0; ng < 4; ng++) {
            uint32_t bfr[2][4];
            #pragma unroll
            for (int kf = 0; kf < 2; kf++)
                ldsm4(bfr[kf], Bsb + (brow + ng*16)*40 + kf*16 + bcol);
            #pragma unroll
            for (int s = 0; s < 2; s++) {
                int nf = ng*2 + s;
                #pragma unroll
                for (int mf = 0; mf < 2; mf++) {
                    mmabf(acc[mf][nf], af[mf][0], bfr[0][2*s], bfr[0][2*s+1]);
                    mmabf(acc[mf][nf], af[mf][1], bfr[1][2*s], bfr[1][2*s+1]);
                }
            }
        }
    }

    const int mrow = m0 + wm*32 + (lane >> 2);
    const int ocol = o0 + wn*64 + (lane & 3)*2;
    if (MODE == 0) {
        #pragma unroll
        for (int mf = 0; mf < 2; mf++) {
            int r0 = mrow + mf*16, r1 = r0 + 8;
            float rs0 = g_rs[r0], mr0 = g_mu[r0]*rs0;
            float rs1 = g_rs[r1], mr1 = g_mu[r1]*rs1;
            #pragma unroll
            for (int nf = 0; nf < 8; nf++) {
                int c = ocol + nf*8;
                float sq0 = g_Sq[n*Dd + c], sq1 = g_Sq[n*Dd + c + 1];
                float cq0 = g_Cq[n*Dd + c], cq1 = g_Cq[n*Dd + c + 1];
                float* d = acc[mf][nf];
                *(uint32_t*)(g_Qh + (size_t)r0*Dd + c) =
                    pk2(rs0*d[0] - mr0*sq0 + cq0, rs0*d[1] - mr0*sq1 + cq1);
                *(uint32_t*)(g_Qh + (size_t)r1*Dd + c) =
                    pk2(rs1*d[2] - mr1*sq0 + cq0, rs1*d[3] - mr1*sq1 + cq1);
            }
        }
    } else {
        float mfv = g_maskf[n];
        #pragma unroll
        for (int mf = 0; mf < 2; mf++) {
            int r0 = mrow + mf*16, r1 = r0 + 8;
            #pragma unroll
            for (int nf = 0; nf < 8; nf++) {
                int c = ocol + nf*8;
                float* d = acc[mf][nf];
                float2 x0 = *(const float2*)(X + (size_t)r0*Dd + c);
                float2 x1 = *(const float2*)(X + (size_t)r1*Dd + c);
                *(float2*)(Out + (size_t)r0*Dd + c) =
                    make_float2(x0.x + mfv*d[0], x0.y + mfv*d[1]);
                *(float2*)(Out + (size_t)r1*Dd + c) =
                    make_float2(x1.x + mfv*d[2], x1.y + mfv*d[3]);
            }
        }
    }
}

// ------- kv-compress: bf16x3 tensor cores, cp.async, + LN + mask + quant --------
__global__ __launch_bounds__(256) void k_kvmma()
{
    extern __shared__ __nv_bfloat16 kvs[];
    const int m0 = blockIdx.x * 128;
    const int n  = m0 >> 12;
    const int tid = threadIdx.x, lane = tid & 31, warp = tid >> 5;
    const int wm = warp & 3, wn = warp >> 2;

    const __nv_bfloat16* srcs[4] = {
        g_xh + (size_t)m0*Dd, g_xl + (size_t)m0*Dd,
        g_Mbh + (size_t)(n*128)*Dd, g_Mbl + (size_t)(n*128)*Dd };

    auto copyS = [&](int st, int k0) {
        __nv_bfloat16* base = kvs + (size_t)st*4*5120;
        #pragma unroll
        for (int op = 0; op < 4; op++) {
            #pragma unroll
            for (int i = 0; i < 2; i++) {
                int idx = tid + i*256;
                int r = idx >> 2, c = (idx & 3) * 8;
                cpa16(base + op*5120 + r*40 + c, srcs[op] + (size_t)r*Dd + k0 + c);
            }
        }
    };

    copyS(0, 0);
    CPCOMMIT();

    float acc[2][8][4];
    #pragma unroll
    for (int i = 0; i < 2; i++)
        #pragma unroll
        for (int j = 0; j < 8; j++)
            #pragma unroll
            for (int k = 0; k < 4; k++) acc[i][j][k] = 0.f;

    const int arow = wm*32 + (lane & 15);
    const int acol = ((lane >> 4) & 1) * 8;
    const int brow = wn*64 + (lane & 7) + ((lane >> 4) & 1) * 8;
    const int bcol = ((lane >> 3) & 1) * 8;

    for (int ks = 0; ks < 16; ks++) {
        int st = ks & 1;
        CPWAIT0();
        __syncthreads();
        if (ks < 15) { copyS(st ^ 1, (ks+1)*32); CPCOMMIT(); }

        const __nv_bfloat16* Ahs = kvs + (size_t)st*4*5120;
        const __nv_bfloat16* Als = Ahs + 5120;
        const __nv_bfloat16* Bhs = Ahs + 2*5120;
        const __nv_bfloat16* Bls = Ahs + 3*5120;

        uint32_t ah[2][2][4], al[2][2][4];
        #pragma unroll
        for (int mf = 0; mf < 2; mf++)
            #pragma unroll
            for (int kf = 0; kf < 2; kf++) {
                ldsm4(ah[mf][kf], Ahs + (arow + mf*16)*40 + kf*16 + acol);
                ldsm4(al[mf][kf], Als + (arow + mf*16)*40 + kf*16 + acol);
            }

        #pragma unroll
        for (int ng = 0; ng < 4; ng++) {
            uint32_t bh[2][4], bl[2][4];
            #pragma unroll
            for (int kf = 0; kf < 2; kf++) {
                ldsm4(bh[kf], Bhs + (brow + ng*16)*40 + kf*16 + bcol);
                ldsm4(bl[kf], Bls + (brow + ng*16)*40 + kf*16 + bcol);
            }
            #pragma unroll
            for (int s = 0; s < 2; s++) {
                int nf = ng*2 + s;
                #pragma unroll
                for (int mf = 0; mf < 2; mf++) {
                    mmabf(acc[mf][nf], ah[mf][0], bh[0][2*s], bh[0][2*s+1]);
                    mmabf(acc[mf][nf], ah[mf][1], bh[1][2*s], bh[1][2*s+1]);
                    mmabf(acc[mf][nf], ah[mf][0], bl[0][2*s], bl[0][2*s+1]);
                    mmabf(acc[mf][nf], ah[mf][1], bl[1][2*s], bl[1][2*s+1]);
                    mmabf(acc[mf][nf], al[mf][0], bh[0][2*s], bh[0][2*s+1]);
                    mmabf(acc[mf][nf], al[mf][1], bh[1][2*s], bh[1][2*s+1]);
                }
            }
        }
    }

    const float mfv = g_maskf[n];
    const int mrow = m0 + wm*32 + (lane >> 2);
    float smv[16], cmv[16];
    #pragma unroll
    for (int nf = 0; nf < 8; nf++) {
        int o = wn*64 + nf*8 + (lane & 3)*2;
        smv[2*nf]   = g_SM[n*128 + o];   smv[2*nf+1] = g_SM[n*128 + o + 1];
        cmv[2*nf]   = g_CM[n*128 + o];   cmv[2*nf+1] = g_CM[n*128 + o + 1];
    }
    float* dstb = (wn == 0) ? g_kq : g_vq;
    #pragma unroll
    for (int mf2 = 0; mf2 < 2; mf2++) {
        #pragma unroll
        for (int rr = 0; rr < 2; rr++) {
            int r = mrow + mf2*16 + rr*8;
            float rsv = g_rs[r], murs = g_mu[r]*rsv;
            float v[16]; float am = 0.f;
            #pragma unroll
            for (int nf = 0; nf < 8; nf++) {
                #pragma unroll
                for (int t = 0; t < 2; t++) {
                    float val = (rsv*acc[mf2][nf][2*rr+t] - murs*smv[2*nf+t] + cmv[2*nf+t]) * mfv;
                    v[2*nf+t] = val;
                    am = fmaxf(am, fabsf(val));
                }
            }
            am = fmaxf(am, __shfl_xor_sync(0xffffffffu, am, 1));
            am = fmaxf(am, __shfl_xor_sync(0xffffffffu, am, 2));
            am = fmaxf(am, 1e-8f);
            float scq = 127.f / am;
            float inv = am * (1.f / 127.f);
            #pragma unroll
            for (int nf = 0; nf < 8; nf++) {
                float q0 = rintf(v[2*nf]   * scq) * inv;
                float q1 = rintf(v[2*nf+1] * scq) * inv;
                *(float2*)(dstb + (size_t)r*64 + nf*8 + (lane & 3)*2) = make_float2(q0, q1);
            }
        }
    }
}

// ---------------- transpose decoders ----------------
__global__ void k_transdec(const float* __restrict__ kd, const float* __restrict__ vd)
{
    int idx = blockIdx.x * 256 + threadIdx.x;
    int d = idx >> 6, r = idx & 63;
    g_kdecT[r*Dd + d] = kd[idx];
    g_vdecT[r*Dd + d] = vd[idx];
}

// ---------------- average over n + decompress -> bf16 K/V ----------------
__global__ __launch_bounds__(256) void k_decomp()
{
    __shared__ float avg[16][64];
    int bt0 = blockIdx.x * 16;
    int isv = blockIdx.y;
    const float* src = isv ? g_vq : g_kq;
    const float* dec = isv ? g_vdecT : g_kdecT;
    __nv_bfloat16* dstb = isv ? g_Vh : g_Kh;
    float invna = g_invna;
    int tid = threadIdx.x;
    #pragma unroll
    for (int j = 0; j < 4; j++) {
        int p = j*256 + tid;
        int row = p >> 6, r = p & 63;
        float s = 0.f;
        #pragma unroll
        for (int n = 0; n < Nn; n++)
            s += src[((size_t)(n*BTc + bt0 + row))*64 + r];
        avg[row][r] = s * invna;
    }
    __syncthreads();
    int d0 = tid * 2;
    float2 acc[16];
    #pragma unroll
    for (int row = 0; row < 16; row++) { acc[row].x = 0.f; acc[row].y = 0.f; }
    for (int r = 0; r < 64; r++) {
        float2 kd = *(const float2*)(dec + r*Dd + d0);
        #pragma unroll
        for (int row = 0; row < 16; row++) {
            float a = avg[row][r];
            acc[row].x = fmaf(a, kd.x, acc[row].x);
            acc[row].y = fmaf(a, kd.y, acc[row].y);
        }
    }
    float sc = isv ? 1.f : INV_SQRT_HD;
    int h = d0 >> 7, hd = d0 & 127;
    #pragma unroll
    for (int row = 0; row < 16; row++) {
        int bt = bt0 + row;
        int b = bt >> 10, t = bt & 1023;
        __nv_bfloat16* dst = dstb + (((size_t)(b*Hh+h)*Tt + t)*HDc + hd);
        *(uint32_t*)dst = pk2(acc[row].x * sc, acc[row].y * sc);
    }
}

// -------- causal flash attention: bf16 mma, paired q-tiles, nbh offset ----------
__global__ __launch_bounds__(128) void k_flash(int nbase)
{
    extern __shared__ __nv_bfloat16 smb[];
    __nv_bfloat16* Qs = smb;
    __nv_bfloat16* KV = Qs + 64*FSTR;
    const int nbh = blockIdx.y + nbase;
    const int n = nbh >> 4, b = (nbh >> 2) & 3, h = nbh & 3;
    const int tid = threadIdx.x, lane = tid & 31, warp = tid >> 5;

    const size_t kvbase = (size_t)(b*Hh + h) * Tt * HDc;
    const int r0q = warp*16 + (lane >> 2);
    const int c0q = (lane & 3) * 2;

    auto copyKV = [&](int buf, int k0) {
        __nv_bfloat16* Kb = KV + (size_t)buf * 2*64*FSTR;
        __nv_bfloat16* Vb = Kb + 64*FSTR;
        #pragma unroll
        for (int i = 0; i < 8; i++) {
            int idx = tid + i*128;
            int r = idx >> 4, c = (idx & 15)*8;
            size_t src = kvbase + (size_t)(k0 + r)*HDc + c;
            cpa16(&Kb[r*FSTR + c], g_Kh + src);
            cpa16(&Vb[r*FSTR + c], g_Vh + src);
        }
    };

    #pragma unroll
    for (int phase = 0; phase < 2; phase++) {
        const int qt = phase ? (NT - 1 - (int)blockIdx.x) : (int)blockIdx.x;
        const int q0 = qt * 64;
        const size_t qbase = ((size_t)(n*Bb + b)*Tt + q0) * Dd + h*HDc;

        if (phase) __syncthreads();

        #pragma unroll
        for (int i = 0; i < 8; i++) {
            int idx = tid + i*128;
            int r = idx >> 4, c = (idx & 15) * 8;
            cpa16(&Qs[r*FSTR + c], g_Qh + qbase + (size_t)r*Dd + c);
        }
        CPCOMMIT();
        copyKV(0, 0);
        CPCOMMIT();
        CPWAIT0();
        __syncthreads();

        uint32_t qf[8][4];
        {
            const __nv_bfloat16* qp = Qs + (warp*16 + (lane & 15))*FSTR + (lane >> 4)*8;
            #pragma unroll
            for (int kf = 0; kf < 8; kf++) ldsm4(qf[kf], qp + kf*16);
        }

        float accO[16][4];
        #pragma unroll
        for (int i = 0; i < 16; i++)
            #pragma unroll
            for (int j = 0; j < 4; j++) accO[i][j] = 0.f;
        float mrow[2] = {-1e30f, -1e30f};
        float lrow[2] = {0.f, 0.f};

        for (int kt = 0; kt <= qt; kt++) {
            if (kt > 0) { CPWAIT0(); __syncthreads(); }
            if (kt < qt) { copyKV((kt+1) & 1, (kt+1)*64); CPCOMMIT(); }

            const __nv_bfloat16* Kb = KV + (size_t)(kt & 1) * 2*64*FSTR;
            const __nv_bfloat16* Vb = Kb + 64*FSTR;

            float sfr[8][4];
            #pragma unroll
            for (int i = 0; i < 8; i++)
                #pragma unroll
                for (int j = 0; j < 4; j++) sfr[i][j] = 0.f;

            {
                const __nv_bfloat16* kp = Kb + ((lane & 7) + ((lane >> 4) & 1)*8)*FSTR
                                             + ((lane >> 3) & 1)*8;
                #pragma unroll
                for (int ng = 0; ng < 4; ng++) {
                    #pragma unroll
                    for (int kf = 0; kf < 8; kf++) {
                        uint32_t bf[4];
                        ldsm4(bf, kp + ng*16*FSTR + kf*16);
                        mmabf(sfr[2*ng],   qf[kf], bf[0], bf[1]);
                        mmabf(sfr[2*ng+1], qf[kf], bf[2], bf[3]);
                    }
                }
            }

            if (kt == qt) {
                #pragma unroll
                for (int j = 0; j < 8; j++) {
                    int cj = 8*j + c0q;
                    #pragma unroll
                    for (int rr = 0; rr < 2; rr++) {
                        int ri = r0q + 8*rr;
                        if (cj     > ri) sfr[j][2*rr]   = -1e30f;
                        if (cj + 1 > ri) sfr[j][2*rr+1] = -1e30f;
                    }
                }
            }

            #pragma unroll
            for (int rr = 0; rr < 2; rr++) {
                float tm = -1e30f;
                #pragma unroll
                for (int j = 0; j < 8; j++)
                    tm = fmaxf(tm, fmaxf(sfr[j][2*rr], sfr[j][2*rr+1]));
                tm = fmaxf(tm, __shfl_xor_sync(0xffffffffu, tm, 1));
                tm = fmaxf(tm, __shfl_xor_sync(0xffffffffu, tm, 2));
                float mnew = fmaxf(mrow[rr], tm);
                float scl = exp2f((mrow[rr] - mnew) * L2E);
                float ps = 0.f;
                #pragma unroll
                for (int j = 0; j < 8; j++) {
                    float e0 = exp2f((sfr[j][2*rr]   - mnew) * L2E);
                    float e1 = exp2f((sfr[j][2*rr+1] - mnew) * L2E);
                    sfr[j][2*rr] = e0; sfr[j][2*rr+1] = e1;
                    ps += e0 + e1;
                }
                ps += __shfl_xor_sync(0xffffffffu, ps, 1);
                ps += __shfl_xor_sync(0xffffffffu, ps, 2);
                lrow[rr] = lrow[rr]*scl + ps;
                mrow[rr] = mnew;
                #pragma unroll
                for (int nf = 0; nf < 16; nf++) {
                    accO[nf][2*rr]   *= scl;
                    accO[nf][2*rr+1] *= scl;
                }
            }

            uint32_t pa[4][4];
            #pragma unroll
            for (int kg = 0; kg < 4; kg++) {
                pa[kg][0] = pk2(sfr[2*kg][0],   sfr[2*kg][1]);
                pa[kg][1] = pk2(sfr[2*kg][2],   sfr[2*kg][3]);
                pa[kg][2] = pk2(sfr[2*kg+1][0], sfr[2*kg+1][1]);
                pa[kg][3] = pk2(sfr[2*kg+1][2], sfr[2*kg+1][3]);
            }

            {
                const __nv_bfloat16* vp = Vb + (lane & 15)*FSTR + (lane >> 4)*8;
                #pragma unroll
                for (int dg = 0; dg < 8; dg++) {
                    #pragma unroll
                    for (int kg = 0; kg < 4; kg++) {
                        uint32_t vb[4];
                        ldsm4t(vb, vp + kg*16*FSTR + dg*16);
                        mmabf(accO[2*dg],   pa[kg], vb[0], vb[1]);
                        mmabf(accO[2*dg+1], pa[kg], vb[2], vb[3]);
                    }
                }
            }
        }

        #pragma unroll
        for (int rr = 0; rr < 2; rr++) {
            float inv = 1.f / lrow[rr];
            size_t row = (size_t)(n*Bb + b)*Tt + q0 + r0q + 8*rr;
            __nv_bfloat16* dst = g_AOh + row*Dd + h*HDc;
            #pragma unroll
            for (int nf = 0; nf < 16; nf++) {
                *(uint32_t*)(dst + 8*nf + c0q) =
                    pk2(accO[nf][2*rr]*inv, accO[nf][2*rr+1]*inv);
            }
        }
    }
}

// ---------------- launch ----------------
extern "C" void kernel_launch(void* const* d_in, const int* in_sizes, int n_in,
                              void* d_out, int out_size)
{
    (void)in_sizes; (void)n_in; (void)out_size;
    const float* x     = (const float*)d_in[0];
    const unsigned char* mask = (const unsigned char*)d_in[1];
    const float* lnkw  = (const float*)d_in[2];
    const float* lnkb  = (const float*)d_in[3];
    const float* lnqw  = (const float*)d_in[4];
    const float* lnqb  = (const float*)d_in[5];
    const float* wk    = (const float*)d_in[6];
    const float* wv    = (const float*)d_in[7];
    const float* wq    = (const float*)d_in[8];
    const float* wo    = (const float*)d_in[9];
    const float* kcomp = (const float*)d_in[10];
    const float* vcomp = (const float*)d_in[11];
    const float* kdec  = (const float*)d_in[12];
    const float* vdec  = (const float*)d_in[13];
    float* out = (float*)d_out;

    static cudaStream_t s1 = nullptr, s2 = nullptr;
    static cudaEvent_t eRoot, eLn, eTd, eH0, eDC, eFB;
    static bool init_done = false;
    if (!init_done) {
        cudaStreamCreateWithFlags(&s1, cudaStreamNonBlocking);
        cudaStreamCreateWithFlags(&s2, cudaStreamNonBlocking);
        cudaEventCreateWithFlags(&eRoot, cudaEventDisableTiming);
        cudaEventCreateWithFlags(&eLn,   cudaEventDisableTiming);
        cudaEventCreateWithFlags(&eTd,   cudaEventDisableTiming);
        cudaEventCreateWithFlags(&eH0,   cudaEventDisableTiming);
        cudaEventCreateWithFlags(&eDC,   cudaEventDisableTiming);
        cudaEventCreateWithFlags(&eFB,   cudaEventDisableTiming);
        cudaFuncSetAttribute(k_flash, cudaFuncAttributeMaxDynamicSharedMemorySize,
                             5*64*FSTR*2);
        cudaFuncSetAttribute(k_kvmma, cudaFuncAttributeMaxDynamicSharedMemorySize,
                             2*4*5120*2);
        init_done = true;
    }

    // fork
    cudaEventRecord(eRoot, 0);
    cudaStreamWaitEvent(s1, eRoot, 0);
    cudaStreamWaitEvent(s2, eRoot, 0);

    // s1: LN stats + x bf16 split, decoder transpose, w_o convert
    k_lnstats<<<NROWS/8, 256, 0, s1>>>(x);
    cudaEventRecord(eLn, s1);
    k_transdec<<<128, 256, 0, s1>>>(kdec, vdec);
    k_convwo<<<Nn*Dd*Dd/4/256, 256, 0, s1>>>(wo);
    cudaEventRecord(eTd, s1);

    // s2: Q-branch fold + full Q projection, then flash-B after decomp
    k_foldQ<<<Nn*Dd/8, 256, 0, s2>>>(lnqw, lnqb, wq);
    cudaStreamWaitEvent(s2, eLn, 0);
    k_hgemm<0><<<dim3(4, NROWS/128), 256, 0, s2>>>(nullptr, nullptr, 0);
    cudaEventRecord(eH0, s2);

    // s0: KV chain
    k_mask<<<1, 32>>>(mask);
    k_compgemm<<<dim3(Nn, 2, 8), 256>>>(kcomp, vcomp, wk, wv);
    k_foldM<<<Nn*128/8, 256>>>(lnkw, lnkb);
    cudaStreamWaitEvent(0, eLn, 0);
    k_kvmma<<<NROWS/128, 256, 2*4*5120*2>>>();
    cudaStreamWaitEvent(0, eTd, 0);
    k_decomp<<<dim3(BTc/16, 2), 256>>>();
    cudaEventRecord(eDC, 0);

    // flash-A (n 0..3) on s0 after Q ready
    cudaStreamWaitEvent(0, eH0, 0);
    k_flash<<<dim3(NT/2, 64), 128, 5*64*FSTR*2>>>(0);

    // flash-B (n 4..7) on s2 (Q done in-stream; wait for K/V via eDC)
    cudaStreamWaitEvent(s2, eDC, 0);
    k_flash<<<dim3(NT/2, 64), 128, 5*64*FSTR*2, s2>>>(64);
    cudaEventRecord(eFB, s2);

    // O-projection: first half overlaps flash-B, second half after eFB
    k_hgemm<1><<<dim3(4, 128), 256>>>(x, out, 0);
    cudaStreamWaitEvent(0, eFB, 0);
    k_hgemm<1><<<dim3(4, 128), 256>>>(x, out, 128);
}